// round 12
// baseline (speedup 1.0000x reference)
#include <cuda_runtime.h>
#include <cstdint>

#define T 128
#define N 1024
#define CSZ 8            // cluster size == grid size (one cluster)
#define LOCR 128         // rows/cols owned per block (N/CSZ)
#define NTHR 1024
#define LMBDA 0.01f
#define PAD 136          // 136 % 32 == 8: conflict-free row & column passes

// ---------------- device scratch (no allocations allowed) ----------------
__device__ float g_Fx[T * N];   // precomputed F @ x_t, [t][i]
__device__ float g_Sx[T];       // precomputed sum(x_t)

// ---------------- smem layout (float offsets) ----------------------------
#define OFF_MB   0                        // 4 mbarriers (u64) = 8 floats
#define OFF_A    8                        // At[i][s] 128*136
#define OFF_B    (OFF_A + 128 * PAD)
#define OFF_X    (OFF_B + 128 * PAD)      // x_t local j slice
#define OFF_FX   (OFF_X + 128)
#define OFF_SX   (OFF_FX + 128)
#define OFF_U    (OFF_SX + 128)
#define OFF_W    (OFF_U + 128)
#define OFF_Z    (OFF_W + 128)
#define OFF_CS   (OFF_Z + 128)            // col scales c_j this step
#define OFF_RS   (OFF_CS + 128)           // row scales r_i this step
#define OFF_EXU  (OFF_RS + 128)           // [8][128] slice partials
#define OFF_EXW  (OFF_EXU + 1024)
#define OFF_EXZ  (OFF_EXW + 1024)
#define OFF_UWB  (OFF_EXZ + 1024)         // [par][rank][128] float2 = 4096 f
#define OFF_ZB   (OFF_UWB + 4096)         // [par][rank][128] = 2048 f
#define SMEM_FLOATS (OFF_ZB + 2048)
#define SMEM_BYTES  (SMEM_FLOATS * 4)     // ~180 KB

// ---------------- cluster / DSMEM helpers --------------------------------
__device__ __forceinline__ uint32_t s2u(const void* p) {
    uint32_t a;
    asm("{ .reg .u64 t; cvta.to.shared.u64 t, %1; cvt.u32.u64 %0, t; }"
        : "=r"(a) : "l"(p));
    return a;
}
__device__ __forceinline__ void st_peer_b64(uint32_t saddr, uint32_t rank, uint64_t v) {
    uint32_t ra;
    asm volatile("mapa.shared::cluster.u32 %0, %1, %2;" : "=r"(ra) : "r"(saddr), "r"(rank));
    asm volatile("st.shared::cluster.b64 [%0], %1;" :: "r"(ra), "l"(v) : "memory");
}
__device__ __forceinline__ void st_peer_f32(uint32_t saddr, uint32_t rank, float v) {
    uint32_t ra;
    asm volatile("mapa.shared::cluster.u32 %0, %1, %2;" : "=r"(ra) : "r"(saddr), "r"(rank));
    asm volatile("st.shared::cluster.f32 [%0], %1;" :: "r"(ra), "f"(v) : "memory");
}
__device__ __forceinline__ void mbar_arrive_peer(uint32_t mbar, uint32_t rank) {
    uint32_t ra;
    asm volatile("mapa.shared::cluster.u32 %0, %1, %2;" : "=r"(ra) : "r"(mbar), "r"(rank));
    asm volatile("mbarrier.arrive.release.cluster.shared::cluster.b64 _, [%0];"
                 :: "r"(ra) : "memory");
}
__device__ __forceinline__ void mbar_wait(uint32_t mbar, uint32_t parity) {
    asm volatile(
        "{\n\t.reg .pred P;\n\t"
        "WL_%=:\n\t"
        "mbarrier.try_wait.parity.acquire.cluster.shared::cta.b64 P, [%0], %1, 0x989680;\n\t"
        "@P bra.uni WD_%=;\n\t"
        "bra.uni WL_%=;\n\t"
        "WD_%=:\n\t}"
        :: "r"(mbar), "r"(parity) : "memory");
}
#define CLUSTER_SYNC() do { \
    asm volatile("barrier.cluster.arrive.aligned;" ::: "memory"); \
    asm volatile("barrier.cluster.wait.aligned;"   ::: "memory"); \
} while (0)

__device__ __forceinline__ float grp8_sum(float v) {
    v += __shfl_xor_sync(0xFFFFFFFFu, v, 1);
    v += __shfl_xor_sync(0xFFFFFFFFu, v, 2);
    v += __shfl_xor_sync(0xFFFFFFFFu, v, 4);
    return v;
}

// ---------------- prologue: Sx[t] = sum_j X[t][j] ------------------------
__global__ void sx_kernel(const float* __restrict__ X) {
    int t = blockIdx.x, l = threadIdx.x;
    float s = 0.0f;
    for (int k = l; k < N; k += 32) s += X[t * N + k];
    #pragma unroll
    for (int o = 16; o; o >>= 1) s += __shfl_xor_sync(0xFFFFFFFFu, s, o);
    if (l == 0) g_Sx[t] = s;
}

// ---------------- prologue: Fx[t][i] = sum_k F[i][k] * X[t][k] -----------
__global__ void gemm_fx(const float* __restrict__ F, const float* __restrict__ X) {
    __shared__ float Ft[32][33];
    __shared__ float Xt[32][33];
    int ib = blockIdx.x, tb = blockIdx.y;
    int tid = threadIdx.x;
    int il = tid & 31;
    int tg = tid >> 5;
    float acc[4] = {0.f, 0.f, 0.f, 0.f};
    for (int kk = 0; kk < N; kk += 32) {
        #pragma unroll
        for (int q = 0; q < 4; q++) {
            int idx = tid + 256 * q;
            int r = idx >> 5, c = idx & 31;
            Ft[r][c] = F[(ib * 32 + r) * N + kk + c];
            Xt[r][c] = X[(tb * 32 + r) * N + kk + c];
        }
        __syncthreads();
        #pragma unroll
        for (int k = 0; k < 32; k++) {
            float f = Ft[il][k];
            #pragma unroll
            for (int m = 0; m < 4; m++)
                acc[m] = fmaf(f, Xt[tg + 8 * m][k], acc[m]);
        }
        __syncthreads();
    }
    #pragma unroll
    for (int m = 0; m < 4; m++)
        g_Fx[(tb * 32 + tg + 8 * m) * N + ib * 32 + il] = acc[m];
}

// ---------------- main low-rank scan: push-based mbarrier exchanges ------
__global__ __launch_bounds__(NTHR, 1) __cluster_dims__(CSZ, 1, 1)
void rf_lr(const float* __restrict__ X, float* __restrict__ out) {
    extern __shared__ float sm[];
    float* At = sm + OFF_A;
    float* Bt = sm + OFF_B;

    const int tid = threadIdx.x;
    const int blk = blockIdx.x;         // == cluster rank
    const int rr  = tid >> 3;           // row in row phases
    const int sub = tid & 7;            // sub-lane in row group
    const int sc  = tid & 127;          // s index in column phases
    const int h   = tid >> 7;           // slice in column phases

    const uint32_t smb   = s2u(sm);
    const uint32_t mb_uw0 = smb + 0,  mb_uw1 = smb + 8;
    const uint32_t mb_z0  = smb + 16, mb_z1  = smb + 24;

    // init: zero state, init mbarriers (count = 8 arrivals/phase)
    for (int i = OFF_A; i < SMEM_FLOATS; i += NTHR)
        if (i + tid < SMEM_FLOATS) sm[i + tid] = 0.0f;
    if (tid == 0) {
        asm volatile("mbarrier.init.shared.b64 [%0], %1;" :: "r"(mb_uw0), "r"(CSZ) : "memory");
        asm volatile("mbarrier.init.shared.b64 [%0], %1;" :: "r"(mb_uw1), "r"(CSZ) : "memory");
        asm volatile("mbarrier.init.shared.b64 [%0], %1;" :: "r"(mb_z0),  "r"(CSZ) : "memory");
        asm volatile("mbarrier.init.shared.b64 [%0], %1;" :: "r"(mb_z1),  "r"(CSZ) : "memory");
    }
    if (tid < 128) sm[OFF_SX + tid] = g_Sx[tid];
    __syncthreads();
    CLUSTER_SYNC();     // peers' smem zeroed + mbarriers live before any push

    // prefetch x_0 / Fx_0
    float x_n = 0.0f, fx_n = 0.0f;
    if (tid < 128) {
        x_n  = X[blk * LOCR + tid];
        fx_n = g_Fx[blk * LOCR + tid];
    }

    for (int t = 0; t < T; t++) {
        const int par = t & 1;

        // ---- wait z(t-1), stage x/Fx, pre-reduce z ----------------------
        if (t > 0) mbar_wait((((t - 1) & 1) ? mb_z1 : mb_z0), ((t - 1) >> 1) & 1);
        if (tid < 128) {
            sm[OFF_X + tid]  = x_n;
            sm[OFF_FX + tid] = fx_n;
            if (t > 0) {
                const float* zb = &sm[OFF_ZB + ((t - 1) & 1) * 1024];
                float z = 0.0f;
                #pragma unroll
                for (int r0 = 0; r0 < CSZ; r0++) z += zb[r0 * 128 + tid];
                sm[OFF_Z + tid] = z;
            }
        }
        __syncthreads();                                   // BAR1

        // ---- B phase: colsum -> c_j ; append x_t ------------------------
        {
            float cs = 0.0f;
            for (int s = sub; s < t; s += 8)
                cs = fmaf(Bt[rr * PAD + s], sm[OFF_Z + s], cs);
            cs = grp8_sum(cs);
            const float c = (cs > 1.0f) ? (1.0f / cs) : 1.0f;
            if (sub == 0) {
                sm[OFF_CS + rr] = c;
                Bt[rr * PAD + t] = sm[OFF_X + rr];
            }
        }
        __syncthreads();                                   // BAR2

        // ---- uw pass: apply c on the fly + writeback, slice partials ----
        {
            float up = 0.0f, wp = 0.0f;
            const int j0 = h * 16;
            #pragma unroll 4
            for (int j = j0; j < j0 + 16; j++) {
                const float b = Bt[j * PAD + sc];
                const float v = (sc < t) ? b * sm[OFF_CS + j] : b;
                Bt[j * PAD + sc] = v;
                up = fmaf(v, sm[OFF_X + j], up);
                wp += v;
            }
            sm[OFF_EXU + h * 128 + sc] = up;
            sm[OFF_EXW + h * 128 + sc] = wp;
        }
        if (t + 1 < T && tid < 128) {                      // overlap prefetch
            x_n  = X[(t + 1) * N + blk * LOCR + tid];
            fx_n = g_Fx[(t + 1) * N + blk * LOCR + tid];
        }
        __syncthreads();                                   // BAR3

        // ---- push (u,w) to all ranks, arrive ----------------------------
        if (tid < 128) {
            float u = 0.0f, w = 0.0f;
            #pragma unroll
            for (int hh = 0; hh < 8; hh++) {
                u += sm[OFF_EXU + hh * 128 + tid];
                w += sm[OFF_EXW + hh * 128 + tid];
            }
            uint64_t pk;
            asm("mov.b64 %0, {%1,%2};" : "=l"(pk) : "f"(u), "f"(w));
            const uint32_t slot = s2u(&sm[OFF_UWB + par * 2048 + blk * 256 + tid * 2]);
            #pragma unroll
            for (int r0 = 0; r0 < CSZ; r0++) st_peer_b64(slot, r0, pk);
            asm volatile("bar.sync 1, 128;" ::: "memory");
            if (tid == 0) {
                const uint32_t mb = par ? mb_uw1 : mb_uw0;
                #pragma unroll
                for (int r0 = 0; r0 < CSZ; r0++) mbar_arrive_peer(mb, r0);
            }
        }
        mbar_wait((par ? mb_uw1 : mb_uw0), (t >> 1) & 1);
        if (tid < 128) {
            float u = 0.0f, w = 0.0f;
            const float2* ub = reinterpret_cast<const float2*>(&sm[OFF_UWB + par * 2048]);
            #pragma unroll
            for (int r0 = 0; r0 < CSZ; r0++) {
                const float2 v = ub[r0 * 128 + tid];
                u += v.x; w += v.y;
            }
            sm[OFF_U + tid] = u;
            sm[OFF_W + tid] = w;
        }
        __syncthreads();                                   // BAR4

        // ---- A phase: out, r_i, append ----------------------------------
        {
            float p = 0.0f, q = 0.0f;
            for (int s = sub; s < t; s += 8) {
                const float a = At[rr * PAD + s];
                p = fmaf(a, sm[OFF_U + s], p);
                q = fmaf(a, sm[OFF_W + s], q);
            }
            p = grp8_sum(p);
            q = grp8_sum(q);
            const float outv = sm[OFF_FX + rr] + p;
            if (sub == 0) out[t * N + blk * LOCR + rr] = outv;
            if (t < T - 1) {
                const float rs = fmaf(LMBDA * outv, sm[OFF_SX + t], q);
                const float r  = (rs > 1.0f) ? (1.0f / rs) : 1.0f;
                if (sub == 0) {
                    sm[OFF_RS + rr]  = r;
                    At[rr * PAD + t] = LMBDA * outv;   // unscaled; z pass scales
                }
            }
        }
        if (t == T - 1) break;
        __syncthreads();                                   // BAR5

        // ---- z pass: apply r on the fly + writeback, partials -----------
        {
            float zp = 0.0f;
            const int i0 = h * 16;
            #pragma unroll 4
            for (int i = i0; i < i0 + 16; i++) {
                const float a = At[i * PAD + sc];
                const float v = (sc <= t) ? a * sm[OFF_RS + i] : a;
                At[i * PAD + sc] = v;
                zp += v;
            }
            sm[OFF_EXZ + h * 128 + sc] = zp;
        }
        __syncthreads();                                   // BAR6

        // ---- push z to all ranks, arrive --------------------------------
        if (tid < 128) {
            float z = 0.0f;
            #pragma unroll
            for (int hh = 0; hh < 8; hh++) z += sm[OFF_EXZ + hh * 128 + tid];
            const uint32_t slot = s2u(&sm[OFF_ZB + par * 1024 + blk * 128 + tid]);
            #pragma unroll
            for (int r0 = 0; r0 < CSZ; r0++) st_peer_f32(slot, r0, z);
            asm volatile("bar.sync 1, 128;" ::: "memory");
            if (tid == 0) {
                const uint32_t mb = par ? mb_z1 : mb_z0;
                #pragma unroll
                for (int r0 = 0; r0 < CSZ; r0++) mbar_arrive_peer(mb, r0);
            }
        }
        // next step's top wait + BAR1 provide all ordering
    }

    CLUSTER_SYNC();   // no CTA exits while peers' remote ops could be in flight
}

// ---------------- launch ---------------------------------------------------
extern "C" void kernel_launch(void* const* d_in, const int* in_sizes, int n_in,
                              void* d_out, int out_size) {
    // inputs [T*N]; in_in_fixed [N*N] (dead); out_in_fixed [N*N] (last)
    const float* X = nullptr;
    const float* F = nullptr;
    for (int i = 0; i < n_in; i++) {
        if (in_sizes[i] == T * N && X == nullptr) X = (const float*)d_in[i];
        if (in_sizes[i] == N * N) F = (const float*)d_in[i];
    }
    float* out = (float*)d_out;

    static bool attr_set = false;
    if (!attr_set) {
        cudaFuncSetAttribute(rf_lr, cudaFuncAttributeMaxDynamicSharedMemorySize,
                             SMEM_BYTES);
        attr_set = true;
    }

    sx_kernel<<<T, 32>>>(X);
    dim3 g(N / 32, T / 32);
    gemm_fx<<<g, 256>>>(F, X);
    rf_lr<<<CSZ, NTHR, SMEM_BYTES>>>(X, out);
}

// round 13
// speedup vs baseline: 1.4524x; 1.4524x over previous
#include <cuda_runtime.h>
#include <cstdint>

#define T 128
#define N 1024
#define CSZ 8            // cluster size == grid size (one cluster)
#define LOCR 128         // rows/cols owned per block (N/CSZ)
#define NTHR 1024
#define LMBDA 0.01f
#define PAD 136          // even (float2) ; 136 % 32 == 8

// ---------------- device scratch (no allocations allowed) ----------------
__device__ float g_Fx[T * N];   // precomputed F @ x_t, [t][i]
__device__ float g_Sx[T];       // precomputed sum(x_t)

// ---------------- smem layout (float offsets) ----------------------------
#define OFF_MB   0                        // 4 mbarriers (u64) = 8 floats
#define OFF_A    8                        // At[i][s] 128*136 = 17408
#define OFF_B    (OFF_A + 128 * PAD)      // Bt[j][s] 17408
#define OFF_X    (OFF_B + 128 * PAD)
#define OFF_FX   (OFF_X + 128)
#define OFF_SX   (OFF_FX + 128)
#define OFF_U    (OFF_SX + 128)
#define OFF_W    (OFF_U + 128)
#define OFF_Z    (OFF_W + 128)
#define OFF_CS   (OFF_Z + 128)            // col scales c_j this step
#define OFF_RS   (OFF_CS + 128)           // row scales r_i this step
#define OFF_EXU  (OFF_RS + 128)           // [16][128] slice partials
#define OFF_EXW  (OFF_EXU + 2048)
#define OFF_EXZ  (OFF_EXW + 2048)
#define OFF_UW2  (OFF_EXZ + 2048)         // [par][128 float2] = 512 f
#define OFF_ZL   (OFF_UW2 + 512)          // [par][128] = 256 f
#define SMEM_FLOATS (OFF_ZL + 256)
#define SMEM_BYTES  (SMEM_FLOATS * 4)     // ~171 KB

// ---------------- cluster / DSMEM helpers --------------------------------
__device__ __forceinline__ uint32_t s2u(const void* p) {
    uint32_t a;
    asm("{ .reg .u64 t; cvta.to.shared.u64 t, %1; cvt.u32.u64 %0, t; }"
        : "=r"(a) : "l"(p));
    return a;
}
__device__ __forceinline__ float ld_peer(uint32_t saddr, uint32_t rank) {
    uint32_t ra; float v;
    asm volatile("mapa.shared::cluster.u32 %0, %1, %2;" : "=r"(ra) : "r"(saddr), "r"(rank));
    asm volatile("ld.shared::cluster.f32 %0, [%1];" : "=f"(v) : "r"(ra));
    return v;
}
__device__ __forceinline__ float2 ld_peer_v2(uint32_t saddr, uint32_t rank) {
    uint32_t ra; float2 v;
    asm volatile("mapa.shared::cluster.u32 %0, %1, %2;" : "=r"(ra) : "r"(saddr), "r"(rank));
    asm volatile("ld.shared::cluster.v2.f32 {%0,%1}, [%2];"
                 : "=f"(v.x), "=f"(v.y) : "r"(ra));
    return v;
}
__device__ __forceinline__ void mbar_arrive_peer(uint32_t mbar, uint32_t rank) {
    uint32_t ra;
    asm volatile("mapa.shared::cluster.u32 %0, %1, %2;" : "=r"(ra) : "r"(mbar), "r"(rank));
    asm volatile("mbarrier.arrive.release.cluster.shared::cluster.b64 _, [%0];"
                 :: "r"(ra) : "memory");
}
__device__ __forceinline__ void mbar_wait(uint32_t mbar, uint32_t parity) {
    asm volatile(
        "{\n\t.reg .pred P;\n\t"
        "WL_%=:\n\t"
        "mbarrier.try_wait.parity.acquire.cluster.shared::cta.b64 P, [%0], %1, 0x989680;\n\t"
        "@P bra.uni WD_%=;\n\t"
        "bra.uni WL_%=;\n\t"
        "WD_%=:\n\t}"
        :: "r"(mbar), "r"(parity) : "memory");
}
#define CLUSTER_SYNC() do { \
    asm volatile("barrier.cluster.arrive.aligned;" ::: "memory"); \
    asm volatile("barrier.cluster.wait.aligned;"   ::: "memory"); \
} while (0)

__device__ __forceinline__ float grp8_sum(float v) {
    v += __shfl_xor_sync(0xFFFFFFFFu, v, 1);
    v += __shfl_xor_sync(0xFFFFFFFFu, v, 2);
    v += __shfl_xor_sync(0xFFFFFFFFu, v, 4);
    return v;
}

// ---------------- prologue: Sx[t] = sum_j X[t][j] ------------------------
__global__ void sx_kernel(const float* __restrict__ X) {
    int t = blockIdx.x, l = threadIdx.x;
    float s = 0.0f;
    for (int k = l; k < N; k += 32) s += X[t * N + k];
    #pragma unroll
    for (int o = 16; o; o >>= 1) s += __shfl_xor_sync(0xFFFFFFFFu, s, o);
    if (l == 0) g_Sx[t] = s;
}

// ---------------- prologue: Fx[t][i] = sum_k F[i][k] * X[t][k] -----------
__global__ void gemm_fx(const float* __restrict__ F, const float* __restrict__ X) {
    __shared__ float Ft[32][33];
    __shared__ float Xt[32][33];
    int ib = blockIdx.x, tb = blockIdx.y;
    int tid = threadIdx.x;
    int il = tid & 31;
    int tg = tid >> 5;
    float acc[4] = {0.f, 0.f, 0.f, 0.f};
    for (int kk = 0; kk < N; kk += 32) {
        #pragma unroll
        for (int q = 0; q < 4; q++) {
            int idx = tid + 256 * q;
            int r = idx >> 5, c = idx & 31;
            Ft[r][c] = F[(ib * 32 + r) * N + kk + c];
            Xt[r][c] = X[(tb * 32 + r) * N + kk + c];
        }
        __syncthreads();
        #pragma unroll
        for (int k = 0; k < 32; k++) {
            float f = Ft[il][k];
            #pragma unroll
            for (int m = 0; m < 4; m++)
                acc[m] = fmaf(f, Xt[tg + 8 * m][k], acc[m]);
        }
        __syncthreads();
    }
    #pragma unroll
    for (int m = 0; m < 4; m++)
        g_Fx[(tb * 32 + tg + 8 * m) * N + ib * 32 + il] = acc[m];
}

// ---------------- main low-rank scan: pull + mbarrier signaling ----------
__global__ __launch_bounds__(NTHR, 1) __cluster_dims__(CSZ, 1, 1)
void rf_lr(const float* __restrict__ X, float* __restrict__ out) {
    extern __shared__ float sm[];
    float* At = sm + OFF_A;
    float* Bt = sm + OFF_B;

    const int tid = threadIdx.x;
    const int blk = blockIdx.x;         // == cluster rank
    const int rr  = tid >> 3;           // row in row phases
    const int sub = tid & 7;            // sub-lane in row group
    const int h   = tid >> 6;           // slice (0..15) in column phases
    const int sc2 = (tid & 63) * 2;     // even s index in column phases

    const uint32_t smb    = s2u(sm);
    const uint32_t mb_uw0 = smb + 0,  mb_uw1 = smb + 8;
    const uint32_t mb_z0  = smb + 16, mb_z1  = smb + 24;

    for (int i = OFF_A; i < SMEM_FLOATS; i += NTHR)
        if (i + tid < SMEM_FLOATS) sm[i + tid] = 0.0f;
    if (tid == 0) {
        asm volatile("mbarrier.init.shared.b64 [%0], %1;" :: "r"(mb_uw0), "r"(CSZ) : "memory");
        asm volatile("mbarrier.init.shared.b64 [%0], %1;" :: "r"(mb_uw1), "r"(CSZ) : "memory");
        asm volatile("mbarrier.init.shared.b64 [%0], %1;" :: "r"(mb_z0),  "r"(CSZ) : "memory");
        asm volatile("mbarrier.init.shared.b64 [%0], %1;" :: "r"(mb_z1),  "r"(CSZ) : "memory");
    }
    if (tid < 128) sm[OFF_SX + tid] = g_Sx[tid];
    __syncthreads();
    CLUSTER_SYNC();     // peers zeroed + mbarriers live before any arrive

    float x_n = 0.0f, fx_n = 0.0f;
    if (tid < 128) {
        x_n  = X[blk * LOCR + tid];
        fx_n = g_Fx[blk * LOCR + tid];
    }

    for (int t = 0; t < T; t++) {
        const int par = t & 1;

        // ---- wait z(t-1) signal; stage x/Fx; pull + reduce z ------------
        if (tid < 128) {
            sm[OFF_X + tid]  = x_n;
            sm[OFF_FX + tid] = fx_n;
            if (t > 0) {
                const int zp = (t - 1) & 1;
                mbar_wait((zp ? mb_z1 : mb_z0), ((t - 1) >> 1) & 1);
                const uint32_t a = s2u(&sm[OFF_ZL + zp * 128 + tid]);
                float z = 0.0f;
                #pragma unroll
                for (int r0 = 0; r0 < CSZ; r0++) z += ld_peer(a, r0);
                sm[OFF_Z + tid] = z;
            }
        }
        __syncthreads();                                   // BAR1

        // ---- B row phase: colsum -> c_j ; append x_t (float2 pairs) -----
        {
            float cs = 0.0f;
            for (int s2 = sub * 2; s2 + 1 < t; s2 += 16) {
                const float2 b = *reinterpret_cast<const float2*>(&Bt[rr * PAD + s2]);
                cs = fmaf(b.x, sm[OFF_Z + s2], cs);
                cs = fmaf(b.y, sm[OFF_Z + s2 + 1], cs);
            }
            if ((t & 1) && sub == (((t - 1) >> 1) & 7))
                cs = fmaf(Bt[rr * PAD + t - 1], sm[OFF_Z + t - 1], cs);
            cs = grp8_sum(cs);
            if (sub == 0) {
                sm[OFF_CS + rr] = (cs > 1.0f) ? (1.0f / cs) : 1.0f;
                Bt[rr * PAD + t] = sm[OFF_X + rr];
            }
        }
        __syncthreads();                                   // BAR2

        // ---- uw column pass: apply c + writeback, slice partials --------
        {
            float u0 = 0.f, u1 = 0.f, w0 = 0.f, w1 = 0.f;
            const int j0 = h * 8;
            #pragma unroll
            for (int j = j0; j < j0 + 8; j++) {
                float2 b = *reinterpret_cast<const float2*>(&Bt[j * PAD + sc2]);
                const float c = sm[OFF_CS + j];
                const float v0 = (sc2     < t) ? b.x * c : b.x;
                const float v1 = (sc2 + 1 < t) ? b.y * c : b.y;
                *reinterpret_cast<float2*>(&Bt[j * PAD + sc2]) = make_float2(v0, v1);
                const float xj = sm[OFF_X + j];
                u0 = fmaf(v0, xj, u0); u1 = fmaf(v1, xj, u1);
                w0 += v0;              w1 += v1;
            }
            sm[OFF_EXU + h * 128 + sc2]     = u0;
            sm[OFF_EXU + h * 128 + sc2 + 1] = u1;
            sm[OFF_EXW + h * 128 + sc2]     = w0;
            sm[OFF_EXW + h * 128 + sc2 + 1] = w1;
        }
        if (t + 1 < T && tid < 128) {                      // overlap prefetch
            x_n  = X[(t + 1) * N + blk * LOCR + tid];
            fx_n = g_Fx[(t + 1) * N + blk * LOCR + tid];
        }
        __syncthreads();                                   // BAR3

        // ---- pre-reduce uw locally, signal, pull ------------------------
        if (tid < 128) {
            float u = 0.0f, w = 0.0f;
            #pragma unroll
            for (int hh = 0; hh < 16; hh++) {
                u += sm[OFF_EXU + hh * 128 + tid];
                w += sm[OFF_EXW + hh * 128 + tid];
            }
            *reinterpret_cast<float2*>(&sm[OFF_UW2 + par * 256 + tid * 2]) =
                make_float2(u, w);
            asm volatile("bar.sync 1, 128;" ::: "memory");
            if (tid < CSZ) mbar_arrive_peer((par ? mb_uw1 : mb_uw0), tid);
            mbar_wait((par ? mb_uw1 : mb_uw0), (t >> 1) & 1);
            const uint32_t a = s2u(&sm[OFF_UW2 + par * 256 + tid * 2]);
            float u2 = 0.0f, w2 = 0.0f;
            #pragma unroll
            for (int r0 = 0; r0 < CSZ; r0++) {
                const float2 v = ld_peer_v2(a, r0);
                u2 += v.x; w2 += v.y;
            }
            sm[OFF_U + tid] = u2;
            sm[OFF_W + tid] = w2;
        }
        __syncthreads();                                   // BAR4

        // ---- A row phase: out, r_i, append (float2 pairs) ---------------
        {
            float p = 0.0f, q = 0.0f;
            for (int s2 = sub * 2; s2 + 1 < t; s2 += 16) {
                const float2 a = *reinterpret_cast<const float2*>(&At[rr * PAD + s2]);
                p = fmaf(a.x, sm[OFF_U + s2], p);
                p = fmaf(a.y, sm[OFF_U + s2 + 1], p);
                q = fmaf(a.x, sm[OFF_W + s2], q);
                q = fmaf(a.y, sm[OFF_W + s2 + 1], q);
            }
            if ((t & 1) && sub == (((t - 1) >> 1) & 7)) {
                const float a = At[rr * PAD + t - 1];
                p = fmaf(a, sm[OFF_U + t - 1], p);
                q = fmaf(a, sm[OFF_W + t - 1], q);
            }
            p = grp8_sum(p);
            q = grp8_sum(q);
            const float outv = sm[OFF_FX + rr] + p;
            if (sub == 0) out[t * N + blk * LOCR + rr] = outv;
            if (t < T - 1 && sub == 0) {
                const float rs = fmaf(LMBDA * outv, sm[OFF_SX + t], q);
                sm[OFF_RS + rr]  = (rs > 1.0f) ? (1.0f / rs) : 1.0f;
                At[rr * PAD + t] = LMBDA * outv;   // z pass applies r
            }
        }
        if (t == T - 1) break;
        __syncthreads();                                   // BAR5

        // ---- z column pass: apply r + writeback, slice partials ---------
        {
            float z0 = 0.f, z1 = 0.f;
            const int i0 = h * 8;
            #pragma unroll
            for (int i = i0; i < i0 + 8; i++) {
                float2 a = *reinterpret_cast<const float2*>(&At[i * PAD + sc2]);
                const float r = sm[OFF_RS + i];
                const float v0 = (sc2     <= t) ? a.x * r : a.x;
                const float v1 = (sc2 + 1 <= t) ? a.y * r : a.y;
                *reinterpret_cast<float2*>(&At[i * PAD + sc2]) = make_float2(v0, v1);
                z0 += v0; z1 += v1;
            }
            sm[OFF_EXZ + h * 128 + sc2]     = z0;
            sm[OFF_EXZ + h * 128 + sc2 + 1] = z1;
        }
        __syncthreads();                                   // BAR6

        // ---- pre-reduce z locally, signal -------------------------------
        if (tid < 128) {
            float z = 0.0f;
            #pragma unroll
            for (int hh = 0; hh < 16; hh++) z += sm[OFF_EXZ + hh * 128 + tid];
            sm[OFF_ZL + par * 128 + tid] = z;
            asm volatile("bar.sync 1, 128;" ::: "memory");
            if (tid < CSZ) mbar_arrive_peer((par ? mb_z1 : mb_z0), tid);
        }
        // consumers wait at top of t+1; BAR1 orders for the rest
    }

    CLUSTER_SYNC();   // no CTA exits while peers' remote ops may be in flight
}

// ---------------- launch ---------------------------------------------------
extern "C" void kernel_launch(void* const* d_in, const int* in_sizes, int n_in,
                              void* d_out, int out_size) {
    // inputs [T*N]; in_in_fixed [N*N] (dead); out_in_fixed [N*N] (last)
    const float* X = nullptr;
    const float* F = nullptr;
    for (int i = 0; i < n_in; i++) {
        if (in_sizes[i] == T * N && X == nullptr) X = (const float*)d_in[i];
        if (in_sizes[i] == N * N) F = (const float*)d_in[i];
    }
    float* out = (float*)d_out;

    static bool attr_set = false;
    if (!attr_set) {
        cudaFuncSetAttribute(rf_lr, cudaFuncAttributeMaxDynamicSharedMemorySize,
                             SMEM_BYTES);
        attr_set = true;
    }

    sx_kernel<<<T, 32>>>(X);
    dim3 g(N / 32, T / 32);
    gemm_fx<<<g, 256>>>(F, X);
    rf_lr<<<CSZ, NTHR, SMEM_BYTES>>>(X, out);
}